// round 14
// baseline (speedup 1.0000x reference)
#include <cuda_runtime.h>
#include <cuda_fp16.h>
#include <math.h>

static constexpr int BATCH = 4;
static constexpr int MG = 4;           // aligned groups
static constexpr int C = 32;
static constexpr int S = 32 * 32 * 32; // spatial voxels
static constexpr float SCALE = 0.17677669529663687f; // 1/sqrt(32)

// ---------------- device scratch (no runtime allocation allowed) --------------
__device__ float g_u[4 * C * S];       // u_j[c,s] for j=0..3 (batch-independent)
__device__ float g_vt[C * S];          // Wv4 @ token
__device__ float g_l4[S];              // token-vs-token logit (batch-independent)
__device__ float g_h[BATCH * 64 * S];  // conv1+gelu intermediate
__device__ unsigned g_wtp1[128 * 125 * 64 / 2]; // conv1 W frag-permuted f16x2
__device__ unsigned g_wtp2[64 * 125 * 32 / 2];  // conv2 W frag-permuted f16x2

// ---------- weight permute: [co][cin][tap] -> [cc][dh][j][mt][lane][q] --------
// Each 32-bit word packs an f16x2 (cin pair) in the exact per-thread
// m16n8k16 A-fragment order (WM always 1 now).
template <int CIN, int COUT, int WM, int MT>
__global__ void k_wtp(const float* __restrict__ w, unsigned* __restrict__ wtp) {
    int n = CIN * 125 * COUT / 2;
    for (int p = blockIdx.x * blockDim.x + threadIdx.x; p < n;
         p += gridDim.x * blockDim.x) {
        int q    = p & 3;
        int lane = (p >> 2) & 31;
        int r    = p >> 7;
        int mt = r % MT; r /= MT;
        int wm = r % WM; r /= WM;
        int j  = r % 25; r /= 25;
        int dh = r % 5;
        int cc = r / 5;
        int gid = lane >> 2, tig = lane & 3;
        int co   = wm * (MT * 16) + mt * 16 + gid + 8 * (q & 1);
        int cin0 = cc * 16 + 2 * tig + 8 * (q >> 1);
        int tap  = dh * 25 + j;
        float lo = w[((size_t)co * CIN + cin0) * 125 + tap];
        float hi = w[((size_t)co * CIN + cin0 + 1) * 125 + tap];
        __half2 hh = __floats2half2_rn(lo, hi);
        wtp[p] = *(unsigned*)&hh;
    }
}

// ---------------- K1: batch-independent attention precompute ------------------
__global__ void k_pre(const float* __restrict__ basis, const float* __restrict__ mixer,
                      const float* __restrict__ wq, const float* __restrict__ wk,
                      const float* __restrict__ wv) {
    __shared__ float smm[C * 8];
    __shared__ float smq[C * C];
    __shared__ float smk[5 * C * C];
    __shared__ float smv[C * C];
    int tid = threadIdx.x;
    for (int t = tid; t < C * 8; t += blockDim.x)     smm[t] = mixer[t];
    for (int t = tid; t < C * C; t += blockDim.x)     smq[t] = wq[4 * C * C + t];
    for (int t = tid; t < 5 * C * C; t += blockDim.x) smk[t] = wk[t];
    for (int t = tid; t < C * C; t += blockDim.x)     smv[t] = wv[4 * C * C + t];
    __syncthreads();

    int s = blockIdx.x * blockDim.x + tid;
    float br[8];
#pragma unroll
    for (int r = 0; r < 8; ++r) br[r] = basis[r * S + s];

    float tok[C];
#pragma unroll
    for (int c = 0; c < C; ++c) {
        float a = 0.f;
#pragma unroll
        for (int r = 0; r < 8; ++r) a += smm[c * 8 + r] * br[r];
        tok[c] = a;
    }
    float q4[C];
#pragma unroll
    for (int o = 0; o < C; ++o) {
        float a = 0.f;
        for (int c = 0; c < C; ++c) a += smq[o * C + c] * tok[c];
        q4[o] = a;
    }
    for (int j = 0; j < 4; ++j) {
        for (int c = 0; c < C; ++c) {
            float a = 0.f;
            for (int o = 0; o < C; ++o) a += q4[o] * smk[(j * C + o) * C + c];
            g_u[(j * C + c) * S + s] = a;
        }
    }
    float l4 = 0.f;
    for (int c = 0; c < C; ++c) {
        float a = 0.f;
        for (int o = 0; o < C; ++o) a += q4[o] * smk[(4 * C + o) * C + c];
        l4 += a * tok[c];
    }
    g_l4[s] = l4 * SCALE;

    for (int c = 0; c < C; ++c) {
        float a = 0.f;
        for (int cp = 0; cp < C; ++cp) a += smv[c * C + cp] * tok[cp];
        g_vt[c * S + s] = a;
    }
}

// ---------------- K2: per-(b,s) attention combine -> out = alpha * att --------
__global__ void k_attn(const float* __restrict__ x, const float* __restrict__ wv,
                       const float* __restrict__ alpha, float* __restrict__ out) {
    __shared__ float smwv[4 * C * C]; // [j][cp][c]
    int tid = threadIdx.x;
    for (int t = tid; t < 4 * C * C; t += blockDim.x) {
        int c  = t % C;
        int cp = (t / C) % C;
        int j  = t / (C * C);
        smwv[t] = wv[(j * C + c) * C + cp];
    }
    __syncthreads();

    int idx = blockIdx.x * blockDim.x + tid;
    int b = idx >> 15;
    int s = idx & (S - 1);
    const float* xb = x + (size_t)b * MG * C * S + s;

    float l[5];
    for (int j = 0; j < 4; ++j) {
        float a = 0.f;
        for (int c = 0; c < C; ++c)
            a += g_u[(j * C + c) * S + s] * xb[(j * C + c) * S];
        l[j] = a * SCALE;
    }
    l[4] = g_l4[s];

    float m = l[0];
#pragma unroll
    for (int j = 1; j < 5; ++j) m = fmaxf(m, l[j]);
    float p[5], sum = 0.f;
#pragma unroll
    for (int j = 0; j < 5; ++j) { p[j] = expf(l[j] - m); sum += p[j]; }
    float inv = 1.f / sum;
#pragma unroll
    for (int j = 0; j < 5; ++j) p[j] *= inv;

    float o_[C];
#pragma unroll
    for (int c = 0; c < C; ++c) o_[c] = p[4] * g_vt[c * S + s];
    for (int j = 0; j < 4; ++j) {
        for (int cp = 0; cp < C; ++cp) {
            float xv = p[j] * xb[(j * C + cp) * S];
            const float* wp = &smwv[(j * C + cp) * C];
#pragma unroll
            for (int c = 0; c < C; ++c) o_[c] += wp[c] * xv;
        }
    }
    float a0 = alpha[0];
#pragma unroll
    for (int c = 0; c < C; ++c)
        out[((size_t)b * C + c) * S + s] = a0 * o_[c];
}

// ======================= fp16 tensor-core conv ================================
// Implicit GEMM, m16n8k16 fp16 mma, f32 accumulate. 128-thread blocks, 4 warps.
// Warp tile: m = MT*16 couts, n = WPW w-positions x 32 d (NT = 4*WPW n8-tiles).
// bytes/mma = 4096/(32*WPW) + 4096/(16*MT): conv1 (MT=4,WPW=1) and conv2
// (MT=2,WPW=2) both hit 192 B/mma vs the 128 B/cyc/SM crossbar.

__device__ __forceinline__ void mma_f16(float* c, const unsigned* a,
                                        unsigned b0, unsigned b1) {
    asm volatile(
        "mma.sync.aligned.m16n8k16.row.col.f32.f16.f16.f32 "
        "{%0,%1,%2,%3}, {%4,%5,%6,%7}, {%8,%9}, {%0,%1,%2,%3};"
        : "+f"(c[0]), "+f"(c[1]), "+f"(c[2]), "+f"(c[3])
        : "r"(a[0]), "r"(a[1]), "r"(a[2]), "r"(a[3]), "r"(b0), "r"(b1));
}

// pick d-dim padding so the kpair-stride of the X tile is ≡ 8 (mod 32) -> the
// 32 lanes of a B-fragment load hit 32 distinct banks.
__host__ __device__ constexpr int pick_pd(int iwt) {
    for (int p = 37; p < 64; ++p)
        if ((5 * iwt * p) % 32 == 8) return p;
    return 37;
}

template <int CIN, int COUT, int WPW, int MT, bool GELU, bool ACCUM>
__global__ __launch_bounds__(128, 2)
void k_conv_tc(const float* __restrict__ in, const unsigned* __restrict__ wtp,
               const float* __restrict__ bias, float* __restrict__ out,
               int h0) {
    constexpr int NT  = 4 * WPW;          // n8-tiles per warp
    constexpr int WT  = 4 * WPW;          // w positions per block (4 warps)
    constexpr int IWT = WT + 4;           // w halo
    constexpr int PD  = pick_pd(IWT);     // padded d dim (36 valid + pad)
    constexpr int XN  = 8 * 5 * IWT * PD; // X tile words (8 kpairs x 5 ih)
    constexpr int WEL = 25 * MT * 128;    // W frag words per (cin16-chunk, dh)
    constexpr int KSTRIDE = 5 * IWT * PD; // kpair stride in X tile (words)

    extern __shared__ unsigned smem_u[];
    unsigned* sx = smem_u;                 // [8][5][IWT][PD] f16x2 words
    uint4*    sw4 = (uint4*)(smem_u + XN); // [25][MT][32] uint4 fragments

    const int bw  = blockIdx.x;
    const int h   = blockIdx.y + h0;
    const int b   = blockIdx.z;
    const int tid = threadIdx.x;
    const int lane = tid & 31, wid = tid >> 5;
    const int gid  = lane >> 2, tig = lane & 3;

    float acc[MT][NT][4];
#pragma unroll
    for (int mt = 0; mt < MT; ++mt)
#pragma unroll
        for (int nt = 0; nt < NT; ++nt)
#pragma unroll
            for (int q = 0; q < 4; ++q) acc[mt][nt][q] = 0.f;

    const float* inb = in + (size_t)b * CIN * S;

    for (int cc = 0; cc < CIN / 16; ++cc) {
        __syncthreads();  // everyone done with previous X (and W)
        // ---- stage X tile: 16 cin as 8 f16x2 pairs, 5 ih rows, halo w,d ----
        for (int idx = tid; idx < XN; idx += 128) {
            int ids = idx % PD;
            int r   = idx / PD;
            int iws = r % IWT; r /= IWT;
            int ihs = r % 5;
            int kp  = r / 5;
            int id = ids - 2, iw = bw * WT + iws - 2, ih = h + ihs - 2;
            float v0 = 0.f, v1 = 0.f;
            if ((unsigned)id < 32u && (unsigned)iw < 32u && (unsigned)ih < 32u) {
                const float* p =
                    inb + (size_t)(cc * 16 + 2 * kp) * S + ih * 1024 + iw * 32 + id;
                v0 = p[0];
                v1 = p[S];
            }
            __half2 hh = __floats2half2_rn(v0, v1);
            sx[idx] = *(unsigned*)&hh;
        }
        for (int dh = 0; dh < 5; ++dh) {
            __syncthreads();  // X visible / previous W use finished
            // ---- stage W fragments: contiguous coalesced uint4 copy ----
            const uint4* wsrc = (const uint4*)(wtp + (size_t)(cc * 5 + dh) * WEL);
#pragma unroll
            for (int idx = tid; idx < WEL / 4; idx += 128)
                sw4[idx] = wsrc[idx];
            __syncthreads();  // W visible

            const unsigned* sxp = sx + ((tig * 5 + dh) * IWT + wid * WPW) * PD + gid;
            const uint4* swp = sw4 + lane;

#pragma unroll
            for (int dw = 0; dw < 5; ++dw) {
#pragma unroll
                for (int dd = 0; dd < 5; ++dd) {
                    const int j = dw * 5 + dd;
                    uint4 a[MT];
#pragma unroll
                    for (int mt = 0; mt < MT; ++mt)
                        a[mt] = swp[(j * MT + mt) * 32];
#pragma unroll
                    for (int nt = 0; nt < NT; ++nt) {
                        const int woff = nt >> 2;
                        const int doff = (nt & 3) * 8;
                        unsigned b0 = sxp[(woff + dw) * PD + dd + doff];
                        unsigned b1 = sxp[4 * KSTRIDE + (woff + dw) * PD + dd + doff];
#pragma unroll
                        for (int mt = 0; mt < MT; ++mt)
                            mma_f16(acc[mt][nt], (const unsigned*)&a[mt], b0, b1);
                    }
                }
            }
        }
    }

    // ---------------- epilogue: bias (+gelu) (+accum) ----------------
#pragma unroll
    for (int mt = 0; mt < MT; ++mt) {
        const int co0 = mt * 16 + gid;
        const float bs0 = bias[co0], bs1 = bias[co0 + 8];
#pragma unroll
        for (int nt = 0; nt < NT; ++nt) {
            const int w_out = bw * WT + wid * WPW + (nt >> 2);
            const int d = (nt & 3) * 8 + 2 * tig;
            float v[4];
            v[0] = acc[mt][nt][0] + bs0;
            v[1] = acc[mt][nt][1] + bs0;
            v[2] = acc[mt][nt][2] + bs1;
            v[3] = acc[mt][nt][3] + bs1;
            if (GELU) {
#pragma unroll
                for (int q = 0; q < 4; ++q)
                    v[q] = 0.5f * v[q] *
                           (1.f + erff(v[q] * 0.70710678118654752f));
            }
            float2* o0 = (float2*)(out +
                ((((size_t)b * COUT + co0) * 32 + h) * 32 + w_out) * 32 + d);
            float2* o1 = (float2*)(out +
                ((((size_t)b * COUT + co0 + 8) * 32 + h) * 32 + w_out) * 32 + d);
            if (ACCUM) {
                float2 e0 = *o0, e1 = *o1;
                v[0] += e0.x; v[1] += e0.y; v[2] += e1.x; v[3] += e1.y;
            }
            *o0 = make_float2(v[0], v[1]);
            *o1 = make_float2(v[2], v[3]);
        }
    }
}

// ------------------------------- launch ---------------------------------------
extern "C" void kernel_launch(void* const* d_in, const int* in_sizes, int n_in,
                              void* d_out, int out_size) {
    const float* x     = (const float*)d_in[0];
    const float* basis = (const float*)d_in[1];
    const float* mixer = (const float*)d_in[2];
    const float* wq    = (const float*)d_in[3];
    const float* wk    = (const float*)d_in[4];
    const float* wv    = (const float*)d_in[5];
    const float* c1w   = (const float*)d_in[6];
    const float* c1b   = (const float*)d_in[7];
    const float* c2w   = (const float*)d_in[8];
    const float* c2b   = (const float*)d_in[9];
    const float* alpha = (const float*)d_in[10];
    float* out = (float*)d_out;

    unsigned *wtp1, *wtp2;
    float *hbuf;
    cudaGetSymbolAddress((void**)&wtp1, g_wtp1);
    cudaGetSymbolAddress((void**)&wtp2, g_wtp2);
    cudaGetSymbolAddress((void**)&hbuf, g_h);

    // conv1: WPW=1, MT=4: X 8*5*8*37 + W 25*4*128   = 98,560 B
    constexpr int SM1 = (8 * 5 * 8 * pick_pd(8) + 25 * 4 * 128) * 4;
    // conv2: WPW=2, MT=2: X 8*5*12*38 + W 25*2*128  = 98,560 B
    constexpr int SM2 = (8 * 5 * 12 * pick_pd(12) + 25 * 2 * 128) * 4;

    cudaFuncSetAttribute((const void*)k_conv_tc<128, 64, 1, 4, true, false>,
                         cudaFuncAttributeMaxDynamicSharedMemorySize, SM1);
    cudaFuncSetAttribute((const void*)k_conv_tc<64, 32, 2, 2, false, true>,
                         cudaFuncAttributeMaxDynamicSharedMemorySize, SM2);

    // One-time host-side resources (created on first, non-captured call).
    static cudaStream_t s1 = nullptr, s2 = nullptr;
    static cudaEvent_t eF = nullptr, eA = nullptr, e1a = nullptr, e2a = nullptr;
    if (s1 == nullptr) {
        cudaStreamCreateWithFlags(&s1, cudaStreamNonBlocking);
        cudaStreamCreateWithFlags(&s2, cudaStreamNonBlocking);
        cudaEventCreateWithFlags(&eF, cudaEventDisableTiming);
        cudaEventCreateWithFlags(&eA, cudaEventDisableTiming);
        cudaEventCreateWithFlags(&e1a, cudaEventDisableTiming);
        cudaEventCreateWithFlags(&e2a, cudaEventDisableTiming);
    }

    // main: weight permutes
    k_wtp<128, 64, 1, 4><<<256, 256>>>(c1w, wtp1);
    k_wtp<64, 32, 1, 2><<<64, 256>>>(c2w, wtp2);
    cudaEventRecord(eF, (cudaStream_t)0);

    // side s1: attention path (overlaps conv1)
    cudaStreamWaitEvent(s1, eF, 0);
    k_pre<<<S / 256, 256, 0, s1>>>(basis, mixer, wq, wk, wv);

    // main: conv1a  h in [0,16)  (captured by ncu)
    k_conv_tc<128, 64, 1, 4, true, false>
        <<<dim3(8, 16, 4), 128, SM1>>>(x, wtp1, c1b, hbuf, 0);
    cudaEventRecord(e1a, (cudaStream_t)0);

    k_attn<<<(BATCH * S) / 256, 256, 0, s1>>>(x, wv, alpha, out);
    cudaEventRecord(eA, s1);

    // main: conv1b  h in [16,32)
    k_conv_tc<128, 64, 1, 4, true, false>
        <<<dim3(8, 16, 4), 128, SM1>>>(x, wtp1, c1b, hbuf, 16);

    // s2: conv2a  h in [0,14) — needs conv1a output rows <=15, attn-out
    cudaStreamWaitEvent(s2, e1a, 0);
    cudaStreamWaitEvent(s2, eA, 0);
    k_conv_tc<64, 32, 2, 2, false, true>
        <<<dim3(4, 14, 4), 128, SM2, s2>>>(hbuf, wtp2, c2b, out, 0);
    cudaEventRecord(e2a, s2);

    // main: conv2b  h in [14,32) — after conv1b (stream order) + attn
    cudaStreamWaitEvent((cudaStream_t)0, eA, 0);
    k_conv_tc<64, 32, 2, 2, false, true>
        <<<dim3(4, 18, 4), 128, SM2>>>(hbuf, wtp2, c2b, out, 14);

    // rejoin s2 into origin stream so the captured graph is complete
    cudaStreamWaitEvent((cudaStream_t)0, e2a, 0);
}

// round 15
// speedup vs baseline: 1.2844x; 1.2844x over previous
#include <cuda_runtime.h>
#include <cuda_fp16.h>
#include <math.h>

static constexpr int BATCH = 4;
static constexpr int MG = 4;           // aligned groups
static constexpr int C = 32;
static constexpr int S = 32 * 32 * 32; // spatial voxels
static constexpr float SCALE = 0.17677669529663687f; // 1/sqrt(32)

// ---------------- device scratch (no runtime allocation allowed) --------------
__device__ float g_u[4 * C * S];       // u_j[c,s] for j=0..3 (batch-independent)
__device__ float g_vt[C * S];          // Wv4 @ token
__device__ float g_l4[S];              // token-vs-token logit (batch-independent)
__device__ float g_h[BATCH * 64 * S];  // conv1+gelu intermediate
__device__ unsigned g_wtp1[128 * 125 * 64 / 2]; // conv1 W frag-permuted f16x2
__device__ unsigned g_wtp2[64 * 125 * 32 / 2];  // conv2 W frag-permuted f16x2

// ---------- weight permute: [co][cin][tap] -> [cc][dh][j][wm][mt][lane][q] ----
// Each 32-bit word packs an f16x2 (cin pair) in the exact per-thread
// m16n8k16 A-fragment order.
template <int CIN, int COUT, int WM, int MT>
__global__ void k_wtp(const float* __restrict__ w, unsigned* __restrict__ wtp) {
    int n = CIN * 125 * COUT / 2;
    for (int p = blockIdx.x * blockDim.x + threadIdx.x; p < n;
         p += gridDim.x * blockDim.x) {
        int q    = p & 3;
        int lane = (p >> 2) & 31;
        int r    = p >> 7;
        int mt = r % MT; r /= MT;
        int wm = r % WM; r /= WM;
        int j  = r % 25; r /= 25;
        int dh = r % 5;
        int cc = r / 5;
        int gid = lane >> 2, tig = lane & 3;
        int co   = wm * (MT * 16) + mt * 16 + gid + 8 * (q & 1);
        int cin0 = cc * 16 + 2 * tig + 8 * (q >> 1);
        int tap  = dh * 25 + j;
        float lo = w[((size_t)co * CIN + cin0) * 125 + tap];
        float hi = w[((size_t)co * CIN + cin0 + 1) * 125 + tap];
        __half2 hh = __floats2half2_rn(lo, hi);
        wtp[p] = *(unsigned*)&hh;
    }
}

// ---------------- K1: batch-independent attention precompute ------------------
__global__ void k_pre(const float* __restrict__ basis, const float* __restrict__ mixer,
                      const float* __restrict__ wq, const float* __restrict__ wk,
                      const float* __restrict__ wv) {
    __shared__ float smm[C * 8];
    __shared__ float smq[C * C];
    __shared__ float smk[5 * C * C];
    __shared__ float smv[C * C];
    int tid = threadIdx.x;
    for (int t = tid; t < C * 8; t += blockDim.x)     smm[t] = mixer[t];
    for (int t = tid; t < C * C; t += blockDim.x)     smq[t] = wq[4 * C * C + t];
    for (int t = tid; t < 5 * C * C; t += blockDim.x) smk[t] = wk[t];
    for (int t = tid; t < C * C; t += blockDim.x)     smv[t] = wv[4 * C * C + t];
    __syncthreads();

    int s = blockIdx.x * blockDim.x + tid;
    float br[8];
#pragma unroll
    for (int r = 0; r < 8; ++r) br[r] = basis[r * S + s];

    float tok[C];
#pragma unroll
    for (int c = 0; c < C; ++c) {
        float a = 0.f;
#pragma unroll
        for (int r = 0; r < 8; ++r) a += smm[c * 8 + r] * br[r];
        tok[c] = a;
    }
    float q4[C];
#pragma unroll
    for (int o = 0; o < C; ++o) {
        float a = 0.f;
        for (int c = 0; c < C; ++c) a += smq[o * C + c] * tok[c];
        q4[o] = a;
    }
    for (int j = 0; j < 4; ++j) {
        for (int c = 0; c < C; ++c) {
            float a = 0.f;
            for (int o = 0; o < C; ++o) a += q4[o] * smk[(j * C + o) * C + c];
            g_u[(j * C + c) * S + s] = a;
        }
    }
    float l4 = 0.f;
    for (int c = 0; c < C; ++c) {
        float a = 0.f;
        for (int o = 0; o < C; ++o) a += q4[o] * smk[(4 * C + o) * C + c];
        l4 += a * tok[c];
    }
    g_l4[s] = l4 * SCALE;

    for (int c = 0; c < C; ++c) {
        float a = 0.f;
        for (int cp = 0; cp < C; ++cp) a += smv[c * C + cp] * tok[cp];
        g_vt[c * S + s] = a;
    }
}

// ---------------- K2: per-(b,s) attention combine -> out = alpha * att --------
__global__ void k_attn(const float* __restrict__ x, const float* __restrict__ wv,
                       const float* __restrict__ alpha, float* __restrict__ out) {
    __shared__ float smwv[4 * C * C]; // [j][cp][c]
    int tid = threadIdx.x;
    for (int t = tid; t < 4 * C * C; t += blockDim.x) {
        int c  = t % C;
        int cp = (t / C) % C;
        int j  = t / (C * C);
        smwv[t] = wv[(j * C + c) * C + cp];
    }
    __syncthreads();

    int idx = blockIdx.x * blockDim.x + tid;
    int b = idx >> 15;
    int s = idx & (S - 1);
    const float* xb = x + (size_t)b * MG * C * S + s;

    float l[5];
    for (int j = 0; j < 4; ++j) {
        float a = 0.f;
        for (int c = 0; c < C; ++c)
            a += g_u[(j * C + c) * S + s] * xb[(j * C + c) * S];
        l[j] = a * SCALE;
    }
    l[4] = g_l4[s];

    float m = l[0];
#pragma unroll
    for (int j = 1; j < 5; ++j) m = fmaxf(m, l[j]);
    float p[5], sum = 0.f;
#pragma unroll
    for (int j = 0; j < 5; ++j) { p[j] = expf(l[j] - m); sum += p[j]; }
    float inv = 1.f / sum;
#pragma unroll
    for (int j = 0; j < 5; ++j) p[j] *= inv;

    float o_[C];
#pragma unroll
    for (int c = 0; c < C; ++c) o_[c] = p[4] * g_vt[c * S + s];
    for (int j = 0; j < 4; ++j) {
        for (int cp = 0; cp < C; ++cp) {
            float xv = p[j] * xb[(j * C + cp) * S];
            const float* wp = &smwv[(j * C + cp) * C];
#pragma unroll
            for (int c = 0; c < C; ++c) o_[c] += wp[c] * xv;
        }
    }
    float a0 = alpha[0];
#pragma unroll
    for (int c = 0; c < C; ++c)
        out[((size_t)b * C + c) * S + s] = a0 * o_[c];
}

// ======================= fp16 tensor-core conv ================================
// Implicit GEMM, m16n8k16 fp16 mma, f32 accumulate. R10 tiling (256 thr,
// warp tile m32n32, 2 CTAs/SM) + cp.async ring pipeline for W fragments:
// each dh's 25 taps split into chunks of 13+12; chunk ch+1 streams L2->smem
// via LDGSTS while mma crunches chunk ch. W staging leaves the critical path.

__device__ __forceinline__ void mma_f16(float* c, const unsigned* a,
                                        unsigned b0, unsigned b1) {
    asm volatile(
        "mma.sync.aligned.m16n8k16.row.col.f32.f16.f16.f32 "
        "{%0,%1,%2,%3}, {%4,%5,%6,%7}, {%8,%9}, {%0,%1,%2,%3};"
        : "+f"(c[0]), "+f"(c[1]), "+f"(c[2]), "+f"(c[3])
        : "r"(a[0]), "r"(a[1]), "r"(a[2]), "r"(a[3]), "r"(b0), "r"(b1));
}

__device__ __forceinline__ void cp_async16(void* sdst, const void* gsrc) {
    unsigned sa = (unsigned)__cvta_generic_to_shared(sdst);
    asm volatile("cp.async.cg.shared.global [%0], [%1], 16;"
                 :: "r"(sa), "l"(gsrc));
}
__device__ __forceinline__ void cp_commit() {
    asm volatile("cp.async.commit_group;");
}
__device__ __forceinline__ void cp_wait0() {
    asm volatile("cp.async.wait_group 0;");
}

// pick d-dim padding so the kpair-stride of the X tile is ≡ 8 (mod 32) -> the
// 32 lanes of a B-fragment load hit 32 distinct banks.
__host__ __device__ constexpr int pick_pd(int iwt) {
    for (int p = 37; p < 64; ++p)
        if ((5 * iwt * p) % 32 == 8) return p;
    return 37;
}

template <int CIN, int COUT, int WT, int WM, bool GELU, bool ACCUM>
__global__ __launch_bounds__(256, 2)
void k_conv_tc(const float* __restrict__ in, const unsigned* __restrict__ wtp,
               const float* __restrict__ bias, float* __restrict__ out,
               int h0) {
    constexpr int WN  = 8 / WM;           // warps along n (= w positions/block)
    static_assert(WN == WT, "one w per n-warp");
    constexpr int MT  = COUT / (16 * WM); // m16-tiles per warp
    constexpr int NT  = 4;                // n8-tiles per warp (n = 32 d)
    constexpr int IWT = WT + 4;           // w halo
    constexpr int PD  = pick_pd(IWT);     // padded d dim (36 valid + pad)
    constexpr int XN  = 8 * 5 * IWT * PD; // X tile words (8 kpairs x 5 ih)
    constexpr int WEL = 25 * WM * MT * 128; // W frag words per (cin16-chunk, dh)
    constexpr int KSTRIDE = 5 * IWT * PD; // kpair stride in X tile (words)
    constexpr int CH0 = 13, CH1 = 12;     // taps per chunk
    constexpr int CU4_0 = CH0 * WM * MT * 32; // uint4 per chunk0
    constexpr int CU4_1 = CH1 * WM * MT * 32; // uint4 per chunk1
    constexpr int NCC = CIN / 16;

    extern __shared__ unsigned smem_u[];
    unsigned* sx = smem_u;                 // [8][5][IWT][PD] f16x2 words
    uint4* swb0 = (uint4*)(smem_u + XN);   // W ring slot 0 (13 taps max)
    uint4* swb1 = swb0 + CU4_0;            // W ring slot 1

    const int bw  = blockIdx.x;
    const int h   = blockIdx.y + h0;
    const int b   = blockIdx.z;
    const int tid = threadIdx.x;
    const int lane = tid & 31, wid = tid >> 5;
    const int gid  = lane >> 2, tig = lane & 3;
    const int wm = wid % WM, wn = wid / WM;
    const int mb = wm * (MT * 16);

    const uint4* wg = (const uint4*)wtp;

    // prefetch W chunk (cc, ch) into dst via cp.async (uniform across block)
    auto prefetch = [&](int cc, int ch, uint4* dst) {
        const uint4* src = wg +
            ((size_t)(cc * 5 + (ch >> 1)) * WEL) / 4 +
            (size_t)(ch & 1) * CU4_0;
        int n = (ch & 1) ? CU4_1 : CU4_0;
        for (int i = tid; i < n; i += 256) cp_async16(dst + i, src + i);
        cp_commit();
    };

    float acc[MT][NT][4];
#pragma unroll
    for (int mt = 0; mt < MT; ++mt)
#pragma unroll
        for (int nt = 0; nt < NT; ++nt)
#pragma unroll
            for (int q = 0; q < 4; ++q) acc[mt][nt][q] = 0.f;

    const float* inb = in + (size_t)b * CIN * S;

    // first W chunk in flight before anything else
    prefetch(0, 0, swb0);

    for (int cc = 0; cc < NCC; ++cc) {
        if (cc) __syncthreads();  // all mma of prev cc done before X restage
        // ---- stage X tile: 16 cin as 8 f16x2 pairs, 5 ih rows, halo w,d ----
        for (int idx = tid; idx < XN; idx += 256) {
            int ids = idx % PD;
            int r   = idx / PD;
            int iws = r % IWT; r /= IWT;
            int ihs = r % 5;
            int kp  = r / 5;
            int id = ids - 2, iw = bw * WT + iws - 2, ih = h + ihs - 2;
            float v0 = 0.f, v1 = 0.f;
            if ((unsigned)id < 32u && (unsigned)iw < 32u && (unsigned)ih < 32u) {
                const float* p =
                    inb + (size_t)(cc * 16 + 2 * kp) * S + ih * 1024 + iw * 32 + id;
                v0 = p[0];
                v1 = p[S];
            }
            __half2 hh = __floats2half2_rn(v0, v1);
            sx[idx] = *(unsigned*)&hh;
        }

        for (int ch = 0; ch < 10; ++ch) {
            cp_wait0();         // chunk ch landed (had a whole mma phase)
            __syncthreads();    // visible to all; prev chunk's readers done
            if (ch < 9)
                prefetch(cc, ch + 1, (ch & 1) ? swb0 : swb1);
            else if (cc + 1 < NCC)
                prefetch(cc + 1, 0, swb0);   // swb0 free: last read at ch==8

            const int dh = ch >> 1;
            const unsigned* sxp =
                sx + ((tig * 5 + dh) * IWT + wn) * PD + gid;
            const uint4* swp =
                ((ch & 1) ? swb1 : swb0) + wm * MT * 32 + lane;
            const int jbase = (ch & 1) ? CH0 : 0;
            const int jn = (ch & 1) ? CH1 : CH0;

#pragma unroll
            for (int jl = 0; jl < CH0; ++jl) {
                if (jl >= jn) break;
                const int jg = jbase + jl;
                const int dwv = jg / 5, ddv = jg % 5;
                uint4 a[MT];
#pragma unroll
                for (int mt = 0; mt < MT; ++mt)
                    a[mt] = swp[(jl * WM * MT + mt) * 32];
#pragma unroll
                for (int nt = 0; nt < NT; ++nt) {
                    unsigned b0 = sxp[dwv * PD + ddv + nt * 8];
                    unsigned b1 = sxp[4 * KSTRIDE + dwv * PD + ddv + nt * 8];
#pragma unroll
                    for (int mt = 0; mt < MT; ++mt)
                        mma_f16(acc[mt][nt], (const unsigned*)&a[mt], b0, b1);
                }
            }
        }
    }

    // ---------------- epilogue: bias (+gelu) (+accum) ----------------
    const int w_out = bw * WT + wn;
#pragma unroll
    for (int mt = 0; mt < MT; ++mt) {
        const int co0 = mb + mt * 16 + gid;
        const float bs0 = bias[co0], bs1 = bias[co0 + 8];
#pragma unroll
        for (int nt = 0; nt < NT; ++nt) {
            const int d = nt * 8 + 2 * tig;
            float v[4];
            v[0] = acc[mt][nt][0] + bs0;
            v[1] = acc[mt][nt][1] + bs0;
            v[2] = acc[mt][nt][2] + bs1;
            v[3] = acc[mt][nt][3] + bs1;
            if (GELU) {
#pragma unroll
                for (int q = 0; q < 4; ++q)
                    v[q] = 0.5f * v[q] *
                           (1.f + erff(v[q] * 0.70710678118654752f));
            }
            float2* o0 = (float2*)(out +
                ((((size_t)b * COUT + co0) * 32 + h) * 32 + w_out) * 32 + d);
            float2* o1 = (float2*)(out +
                ((((size_t)b * COUT + co0 + 8) * 32 + h) * 32 + w_out) * 32 + d);
            if (ACCUM) {
                float2 e0 = *o0, e1 = *o1;
                v[0] += e0.x; v[1] += e0.y; v[2] += e1.x; v[3] += e1.y;
            }
            *o0 = make_float2(v[0], v[1]);
            *o1 = make_float2(v[2], v[3]);
        }
    }
}

// ------------------------------- launch ---------------------------------------
extern "C" void kernel_launch(void* const* d_in, const int* in_sizes, int n_in,
                              void* d_out, int out_size) {
    const float* x     = (const float*)d_in[0];
    const float* basis = (const float*)d_in[1];
    const float* mixer = (const float*)d_in[2];
    const float* wq    = (const float*)d_in[3];
    const float* wk    = (const float*)d_in[4];
    const float* wv    = (const float*)d_in[5];
    const float* c1w   = (const float*)d_in[6];
    const float* c1b   = (const float*)d_in[7];
    const float* c2w   = (const float*)d_in[8];
    const float* c2b   = (const float*)d_in[9];
    const float* alpha = (const float*)d_in[10];
    float* out = (float*)d_out;

    unsigned *wtp1, *wtp2;
    float *hbuf;
    cudaGetSymbolAddress((void**)&wtp1, g_wtp1);
    cudaGetSymbolAddress((void**)&wtp2, g_wtp2);
    cudaGetSymbolAddress((void**)&hbuf, g_h);

    // conv1: X 8*5*8*37 + W ring 2*13*2*2*128       = 100,608 B
    constexpr int SM1 = (8 * 5 * 8 * pick_pd(8)) * 4 + 2 * 13 * 2 * 2 * 128 * 4;
    // conv2: X 8*5*12*38 + W ring 2*13*1*2*128      =  99,584 B
    constexpr int SM2 = (8 * 5 * 12 * pick_pd(12)) * 4 + 2 * 13 * 1 * 2 * 128 * 4;

    cudaFuncSetAttribute((const void*)k_conv_tc<128, 64, 4, 2, true, false>,
                         cudaFuncAttributeMaxDynamicSharedMemorySize, SM1);
    cudaFuncSetAttribute((const void*)k_conv_tc<64, 32, 8, 1, false, true>,
                         cudaFuncAttributeMaxDynamicSharedMemorySize, SM2);

    // One-time host-side resources (created on first, non-captured call).
    static cudaStream_t s1 = nullptr, s2 = nullptr;
    static cudaEvent_t eF = nullptr, eA = nullptr, e1a = nullptr, e2a = nullptr;
    if (s1 == nullptr) {
        cudaStreamCreateWithFlags(&s1, cudaStreamNonBlocking);
        cudaStreamCreateWithFlags(&s2, cudaStreamNonBlocking);
        cudaEventCreateWithFlags(&eF, cudaEventDisableTiming);
        cudaEventCreateWithFlags(&eA, cudaEventDisableTiming);
        cudaEventCreateWithFlags(&e1a, cudaEventDisableTiming);
        cudaEventCreateWithFlags(&e2a, cudaEventDisableTiming);
    }

    // main: weight permutes
    k_wtp<128, 64, 2, 2><<<256, 256>>>(c1w, wtp1);
    k_wtp<64, 32, 1, 2><<<64, 256>>>(c2w, wtp2);
    cudaEventRecord(eF, (cudaStream_t)0);

    // side s1: attention path (overlaps conv1)
    cudaStreamWaitEvent(s1, eF, 0);
    k_pre<<<S / 256, 256, 0, s1>>>(basis, mixer, wq, wk, wv);

    // main: conv1a  h in [0,16)  (captured by ncu)
    k_conv_tc<128, 64, 4, 2, true, false>
        <<<dim3(8, 16, 4), 256, SM1>>>(x, wtp1, c1b, hbuf, 0);
    cudaEventRecord(e1a, (cudaStream_t)0);

    k_attn<<<(BATCH * S) / 256, 256, 0, s1>>>(x, wv, alpha, out);
    cudaEventRecord(eA, s1);

    // main: conv1b  h in [16,32)
    k_conv_tc<128, 64, 4, 2, true, false>
        <<<dim3(8, 16, 4), 256, SM1>>>(x, wtp1, c1b, hbuf, 16);

    // s2: conv2a  h in [0,14) — needs conv1a output rows <=15, attn-out
    cudaStreamWaitEvent(s2, e1a, 0);
    cudaStreamWaitEvent(s2, eA, 0);
    k_conv_tc<64, 32, 8, 1, false, true>
        <<<dim3(4, 14, 4), 256, SM2, s2>>>(hbuf, wtp2, c2b, out, 0);
    cudaEventRecord(e2a, s2);

    // main: conv2b  h in [14,32) — after conv1b (stream order) + attn
    cudaStreamWaitEvent((cudaStream_t)0, eA, 0);
    k_conv_tc<64, 32, 8, 1, false, true>
        <<<dim3(4, 18, 4), 256, SM2>>>(hbuf, wtp2, c2b, out, 14);

    // rejoin s2 into origin stream so the captured graph is complete
    cudaStreamWaitEvent((cudaStream_t)0, e2a, 0);
}

// round 17
// speedup vs baseline: 1.6667x; 1.2976x over previous
#include <cuda_runtime.h>
#include <cuda_fp16.h>
#include <math.h>

static constexpr int BATCH = 4;
static constexpr int MG = 4;           // aligned groups
static constexpr int C = 32;
static constexpr int S = 32 * 32 * 32; // spatial voxels
static constexpr float SCALE = 0.17677669529663687f; // 1/sqrt(32)

// ---------------- device scratch (no runtime allocation allowed) --------------
__device__ float g_u[4 * C * S];       // u_j[c,s] for j=0..3 (batch-independent)
__device__ float g_vt[C * S];          // Wv4 @ token
__device__ float g_l4[S];              // token-vs-token logit (batch-independent)
__device__ unsigned g_wtp1[128 * 125 * 64 / 2]; // conv1 W frag-permuted f16x2
__device__ unsigned g_wtp2[64 * 125 * 32 / 2];  // conv2 W frag-permuted f16x2
// padded fp16 inputs: [b][kp][ih 36][iw 38][d 40] half2 (cin-pair) words
__device__ unsigned g_xh1[BATCH * 64 * 36 * 38 * 40]; // conv1 input (from x)
__device__ unsigned g_xh2[BATCH * 32 * 36 * 38 * 40]; // conv2 input (from conv1)

// ---------- weight permute: [co][cin][tap] -> [cc][dh][j][wm][mt][lane][q] ----
template <int CIN, int COUT, int WM, int MT>
__global__ void k_wtp(const float* __restrict__ w, unsigned* __restrict__ wtp) {
    int n = CIN * 125 * COUT / 2;
    for (int p = blockIdx.x * blockDim.x + threadIdx.x; p < n;
         p += gridDim.x * blockDim.x) {
        int q    = p & 3;
        int lane = (p >> 2) & 31;
        int r    = p >> 7;
        int mt = r % MT; r /= MT;
        int wm = r % WM; r /= WM;
        int j  = r % 25; r /= 25;
        int dh = r % 5;
        int cc = r / 5;
        int gid = lane >> 2, tig = lane & 3;
        int co   = wm * (MT * 16) + mt * 16 + gid + 8 * (q & 1);
        int cin0 = cc * 16 + 2 * tig + 8 * (q >> 1);
        int tap  = dh * 25 + j;
        float lo = w[((size_t)co * CIN + cin0) * 125 + tap];
        float hi = w[((size_t)co * CIN + cin0 + 1) * 125 + tap];
        __half2 hh = __floats2half2_rn(lo, hi);
        wtp[p] = *(unsigned*)&hh;
    }
}

// ---------- build padded fp16 conv1 input from x ------------------------------
__global__ void k_xh(const float* __restrict__ x, unsigned* __restrict__ xh) {
    int n = BATCH * 64 * 36 * 38 * 40;
    for (int c = blockIdx.x * blockDim.x + threadIdx.x; c < n;
         c += gridDim.x * blockDim.x) {
        int ds = c % 40; int r = c / 40;
        int iwp = r % 38; r /= 38;
        int ihp = r % 36; r /= 36;
        int kp = r % 64;  int b = r / 64;
        int id = ds - 2, iw = iwp - 2, ih = ihp - 2;
        float v0 = 0.f, v1 = 0.f;
        if ((unsigned)id < 32u && (unsigned)iw < 32u && (unsigned)ih < 32u) {
            const float* p = x + ((size_t)(b * 128 + 2 * kp)) * S
                               + ih * 1024 + iw * 32 + id;
            v0 = p[0];
            v1 = p[S];
        }
        __half2 hh = __floats2half2_rn(v0, v1);
        xh[c] = *(unsigned*)&hh;
    }
}

// ---------- zero a word buffer (pads of g_xh2; valid part overwritten) --------
__global__ void k_zero(unsigned* __restrict__ p, int n4) {
    uint4 z = make_uint4(0, 0, 0, 0);
    for (int c = blockIdx.x * blockDim.x + threadIdx.x; c < n4;
         c += gridDim.x * blockDim.x)
        ((uint4*)p)[c] = z;
}

// ---------------- K1: batch-independent attention precompute ------------------
__global__ void k_pre(const float* __restrict__ basis, const float* __restrict__ mixer,
                      const float* __restrict__ wq, const float* __restrict__ wk,
                      const float* __restrict__ wv) {
    __shared__ float smm[C * 8];
    __shared__ float smq[C * C];
    __shared__ float smk[5 * C * C];
    __shared__ float smv[C * C];
    int tid = threadIdx.x;
    for (int t = tid; t < C * 8; t += blockDim.x)     smm[t] = mixer[t];
    for (int t = tid; t < C * C; t += blockDim.x)     smq[t] = wq[4 * C * C + t];
    for (int t = tid; t < 5 * C * C; t += blockDim.x) smk[t] = wk[t];
    for (int t = tid; t < C * C; t += blockDim.x)     smv[t] = wv[4 * C * C + t];
    __syncthreads();

    int s = blockIdx.x * blockDim.x + tid;
    float br[8];
#pragma unroll
    for (int r = 0; r < 8; ++r) br[r] = basis[r * S + s];

    float tok[C];
#pragma unroll
    for (int c = 0; c < C; ++c) {
        float a = 0.f;
#pragma unroll
        for (int r = 0; r < 8; ++r) a += smm[c * 8 + r] * br[r];
        tok[c] = a;
    }
    float q4[C];
#pragma unroll
    for (int o = 0; o < C; ++o) {
        float a = 0.f;
        for (int c = 0; c < C; ++c) a += smq[o * C + c] * tok[c];
        q4[o] = a;
    }
    for (int j = 0; j < 4; ++j) {
        for (int c = 0; c < C; ++c) {
            float a = 0.f;
            for (int o = 0; o < C; ++o) a += q4[o] * smk[(j * C + o) * C + c];
            g_u[(j * C + c) * S + s] = a;
        }
    }
    float l4 = 0.f;
    for (int c = 0; c < C; ++c) {
        float a = 0.f;
        for (int o = 0; o < C; ++o) a += q4[o] * smk[(4 * C + o) * C + c];
        l4 += a * tok[c];
    }
    g_l4[s] = l4 * SCALE;

    for (int c = 0; c < C; ++c) {
        float a = 0.f;
        for (int cp = 0; cp < C; ++cp) a += smv[c * C + cp] * tok[cp];
        g_vt[c * S + s] = a;
    }
}

// ---------------- K2: per-(b,s) attention combine -> out = alpha * att --------
__global__ void k_attn(const float* __restrict__ x, const float* __restrict__ wv,
                       const float* __restrict__ alpha, float* __restrict__ out) {
    __shared__ float smwv[4 * C * C]; // [j][cp][c]
    int tid = threadIdx.x;
    for (int t = tid; t < 4 * C * C; t += blockDim.x) {
        int c  = t % C;
        int cp = (t / C) % C;
        int j  = t / (C * C);
        smwv[t] = wv[(j * C + c) * C + cp];
    }
    __syncthreads();

    int idx = blockIdx.x * blockDim.x + tid;
    int b = idx >> 15;
    int s = idx & (S - 1);
    const float* xb = x + (size_t)b * MG * C * S + s;

    float l[5];
    for (int j = 0; j < 4; ++j) {
        float a = 0.f;
        for (int c = 0; c < C; ++c)
            a += g_u[(j * C + c) * S + s] * xb[(j * C + c) * S];
        l[j] = a * SCALE;
    }
    l[4] = g_l4[s];

    float m = l[0];
#pragma unroll
    for (int j = 1; j < 5; ++j) m = fmaxf(m, l[j]);
    float p[5], sum = 0.f;
#pragma unroll
    for (int j = 0; j < 5; ++j) { p[j] = expf(l[j] - m); sum += p[j]; }
    float inv = 1.f / sum;
#pragma unroll
    for (int j = 0; j < 5; ++j) p[j] *= inv;

    float o_[C];
#pragma unroll
    for (int c = 0; c < C; ++c) o_[c] = p[4] * g_vt[c * S + s];
    for (int j = 0; j < 4; ++j) {
        for (int cp = 0; cp < C; ++cp) {
            float xv = p[j] * xb[(j * C + cp) * S];
            const float* wp = &smwv[(j * C + cp) * C];
#pragma unroll
            for (int c = 0; c < C; ++c) o_[c] += wp[c] * xv;
        }
    }
    float a0 = alpha[0];
#pragma unroll
    for (int c = 0; c < C; ++c)
        out[((size_t)b * C + c) * S + s] = a0 * o_[c];
}

// ======================= fp16 tensor-core conv ================================
// Implicit GEMM, m16n8k16 fp16 mma, f32 accumulate. 256 thr, warp tile m32n32,
// 2 CTAs/SM. BOTH operand streams are cp.async: W as a 2-slot 13/12-tap ring,
// X as a branch-free flat copy from the padded fp16 global tensor.
// X smem layout: [kp8][ih5][IWT][40] with kp-slab stride KSTRIDE = 5*IWT*40+8
// (== 8 mod 32 -> B-frag lanes (8*tig+gid) hit 32 distinct banks; rows stay
// 16B-aligned for cp.async.16).

__device__ __forceinline__ void mma_f16(float* c, const unsigned* a,
                                        unsigned b0, unsigned b1) {
    asm volatile(
        "mma.sync.aligned.m16n8k16.row.col.f32.f16.f16.f32 "
        "{%0,%1,%2,%3}, {%4,%5,%6,%7}, {%8,%9}, {%0,%1,%2,%3};"
        : "+f"(c[0]), "+f"(c[1]), "+f"(c[2]), "+f"(c[3])
        : "r"(a[0]), "r"(a[1]), "r"(a[2]), "r"(a[3]), "r"(b0), "r"(b1));
}

__device__ __forceinline__ void cp_async16(void* sdst, const void* gsrc) {
    unsigned sa = (unsigned)__cvta_generic_to_shared(sdst);
    asm volatile("cp.async.cg.shared.global [%0], [%1], 16;"
                 :: "r"(sa), "l"(gsrc));
}
__device__ __forceinline__ void cp_commit() {
    asm volatile("cp.async.commit_group;");
}
__device__ __forceinline__ void cp_wait0() {
    asm volatile("cp.async.wait_group 0;");
}

template <int KPG, int COUT, int WT, int WM, bool XH2OUT>
__global__ __launch_bounds__(256, 2)
void k_conv_tc(const unsigned* __restrict__ xin, const unsigned* __restrict__ wtp,
               const float* __restrict__ bias, void* __restrict__ outp,
               int h0) {
    constexpr int WN  = 8 / WM;            // warps along n (= w positions)
    static_assert(WN == WT, "one w per n-warp");
    constexpr int MT  = COUT / (16 * WM);  // m16-tiles per warp
    constexpr int NT  = 4;                 // n8-tiles per warp (n = 32 d)
    constexpr int IWT = WT + 4;            // w halo
    constexpr int KSTRIDE = 5 * IWT * 40 + 8;
    static_assert(KSTRIDE % 32 == 8 && KSTRIDE % 4 == 0, "bank/align");
    constexpr int XN   = 8 * KSTRIDE;      // X tile words
    constexpr int TAP4 = WM * MT * 32;     // uint4 per tap
    constexpr int WEL4 = 25 * TAP4;        // uint4 per (cc,dh)
    constexpr int CU4_0 = 13 * TAP4;
    constexpr int NCC  = KPG / 8;
    constexpr int TC   = 8 * 5 * IWT * 10; // X cp.async 16B chunks per cc

    extern __shared__ unsigned smem_u[];
    unsigned* sx = smem_u;                 // X tile
    uint4* swb0 = (uint4*)(smem_u + XN);   // W ring slot 0 (13 taps)
    uint4* swb1 = swb0 + CU4_0;            // W ring slot 1 (12 taps)

    const int bw  = blockIdx.x;
    const int h   = blockIdx.y + h0;
    const int bq  = blockIdx.z;
    const int tid = threadIdx.x;
    const int lane = tid & 31, wid = tid >> 5;
    const int gid  = lane >> 2, tig = lane & 3;
    const int wm = wid % WM, wn = wid / WM;
    const int mb = wm * (MT * 16);

    const uint4* wg = (const uint4*)wtp;

    auto prefetchW = [&](int cc, int ch, uint4* dst) {
        const uint4* src = wg + (size_t)(cc * 5 + (ch >> 1)) * WEL4
                              + (size_t)(ch & 1) * CU4_0;
        int n = (ch & 1) ? 12 * TAP4 : CU4_0;
        for (int i = tid; i < n; i += 256) cp_async16(dst + i, src + i);
        cp_commit();
    };

    float acc[MT][NT][4];
#pragma unroll
    for (int mt = 0; mt < MT; ++mt)
#pragma unroll
        for (int nt = 0; nt < NT; ++nt)
#pragma unroll
            for (int q = 0; q < 4; ++q) acc[mt][nt][q] = 0.f;

    prefetchW(0, 0, swb0);

    for (int cc = 0; cc < NCC; ++cc) {
        if (cc) __syncthreads();  // all mma of prev cc done before X restage
        // ---- X tile: flat cp.async copy from padded fp16 global ----
        for (int c = tid; c < TC; c += 256) {
            int ci = c % 10;
            int seg = c / 10;
            int iws = seg % IWT; int r = seg / IWT;
            int ihs = r % 5;     int kp = r / 5;
            uint4* dst = (uint4*)(sx + kp * KSTRIDE + (ihs * IWT + iws) * 40) + ci;
            const uint4* src = (const uint4*)(xin +
                ((((size_t)(bq * KPG + cc * 8 + kp)) * 36 + h + ihs) * 38 +
                 bw * WT + iws) * 40) + ci;
            cp_async16(dst, src);
        }
        cp_commit();

        for (int ch = 0; ch < 10; ++ch) {
            cp_wait0();          // current W chunk (and X at ch==0) landed
            __syncthreads();
            if (ch < 9)
                prefetchW(cc, ch + 1, (ch & 1) ? swb0 : swb1);
            else if (cc + 1 < NCC)
                prefetchW(cc + 1, 0, swb0);  // swb0 free (last read ch==8)

            const int dh = ch >> 1;
            const unsigned* sxp = sx + tig * KSTRIDE + (dh * IWT + wn) * 40 + gid;
            const uint4* swp = ((ch & 1) ? swb1 : swb0) + wm * MT * 32 + lane;

            if ((ch & 1) == 0) {
#pragma unroll
                for (int jl = 0; jl < 13; ++jl) {
                    const int dwv = jl / 5, ddv = jl % 5;
                    uint4 a[MT];
#pragma unroll
                    for (int mt = 0; mt < MT; ++mt)
                        a[mt] = swp[(jl * WM * MT + mt) * 32];
#pragma unroll
                    for (int nt = 0; nt < NT; ++nt) {
                        unsigned b0 = sxp[dwv * 40 + ddv + nt * 8];
                        unsigned b1 = sxp[4 * KSTRIDE + dwv * 40 + ddv + nt * 8];
#pragma unroll
                        for (int mt = 0; mt < MT; ++mt)
                            mma_f16(acc[mt][nt], (const unsigned*)&a[mt], b0, b1);
                    }
                }
            } else {
#pragma unroll
                for (int jl = 0; jl < 12; ++jl) {
                    const int jg = 13 + jl;
                    const int dwv = jg / 5, ddv = jg % 5;
                    uint4 a[MT];
#pragma unroll
                    for (int mt = 0; mt < MT; ++mt)
                        a[mt] = swp[(jl * WM * MT + mt) * 32];
#pragma unroll
                    for (int nt = 0; nt < NT; ++nt) {
                        unsigned b0 = sxp[dwv * 40 + ddv + nt * 8];
                        unsigned b1 = sxp[4 * KSTRIDE + dwv * 40 + ddv + nt * 8];
#pragma unroll
                        for (int mt = 0; mt < MT; ++mt)
                            mma_f16(acc[mt][nt], (const unsigned*)&a[mt], b0, b1);
                    }
                }
            }
        }
    }

    // ---------------- epilogue ----------------
    const int w_out = bw * WT + wn;
    if (XH2OUT) {
        // conv1: bias + gelu, write padded fp16 conv2-input tensor (u16 stores)
        __half* hp = (__half*)outp;
#pragma unroll
        for (int mt = 0; mt < MT; ++mt) {
            const int co0 = mb + mt * 16 + gid;
            const float bs0 = bias[co0], bs1 = bias[co0 + 8];
            const int par = co0 & 1;
#pragma unroll
            for (int nt = 0; nt < NT; ++nt) {
                const int d0 = nt * 8 + 2 * tig;
                float v[4];
                v[0] = acc[mt][nt][0] + bs0;
                v[1] = acc[mt][nt][1] + bs0;
                v[2] = acc[mt][nt][2] + bs1;
                v[3] = acc[mt][nt][3] + bs1;
#pragma unroll
                for (int q = 0; q < 4; ++q)
                    v[q] = 0.5f * v[q] *
                           (1.f + erff(v[q] * 0.70710678118654752f));
                size_t s0 = ((((size_t)bq * (COUT / 2) + (co0 >> 1)) * 36 +
                              h + 2) * 38 + w_out + 2) * 40 + d0 + 2;
                size_t s1 = s0 + (size_t)4 * 36 * 38 * 40; // co0+8 -> kp+4
                hp[s0 * 2 + par]       = __float2half_rn(v[0]);
                hp[(s0 + 1) * 2 + par] = __float2half_rn(v[1]);
                hp[s1 * 2 + par]       = __float2half_rn(v[2]);
                hp[(s1 + 1) * 2 + par] = __float2half_rn(v[3]);
            }
        }
    } else {
        // conv2: bias + accumulate into float out
        float* out = (float*)outp;
#pragma unroll
        for (int mt = 0; mt < MT; ++mt) {
            const int co0 = mb + mt * 16 + gid;
            const float bs0 = bias[co0], bs1 = bias[co0 + 8];
#pragma unroll
            for (int nt = 0; nt < NT; ++nt) {
                const int d = nt * 8 + 2 * tig;
                float v[4];
                v[0] = acc[mt][nt][0] + bs0;
                v[1] = acc[mt][nt][1] + bs0;
                v[2] = acc[mt][nt][2] + bs1;
                v[3] = acc[mt][nt][3] + bs1;
                float2* o0 = (float2*)(out +
                    ((((size_t)bq * COUT + co0) * 32 + h) * 32 + w_out) * 32 + d);
                float2* o1 = (float2*)(out +
                    ((((size_t)bq * COUT + co0 + 8) * 32 + h) * 32 + w_out) * 32 + d);
                float2 e0 = *o0, e1 = *o1;
                v[0] += e0.x; v[1] += e0.y; v[2] += e1.x; v[3] += e1.y;
                *o0 = make_float2(v[0], v[1]);
                *o1 = make_float2(v[2], v[3]);
            }
        }
    }
}

// ------------------------------- launch ---------------------------------------
extern "C" void kernel_launch(void* const* d_in, const int* in_sizes, int n_in,
                              void* d_out, int out_size) {
    const float* x     = (const float*)d_in[0];
    const float* basis = (const float*)d_in[1];
    const float* mixer = (const float*)d_in[2];
    const float* wq    = (const float*)d_in[3];
    const float* wk    = (const float*)d_in[4];
    const float* wv    = (const float*)d_in[5];
    const float* c1w   = (const float*)d_in[6];
    const float* c1b   = (const float*)d_in[7];
    const float* c2w   = (const float*)d_in[8];
    const float* c2b   = (const float*)d_in[9];
    const float* alpha = (const float*)d_in[10];
    float* out = (float*)d_out;

    unsigned *wtp1, *wtp2, *xh1, *xh2;
    cudaGetSymbolAddress((void**)&wtp1, g_wtp1);
    cudaGetSymbolAddress((void**)&wtp2, g_wtp2);
    cudaGetSymbolAddress((void**)&xh1, g_xh1);
    cudaGetSymbolAddress((void**)&xh2, g_xh2);

    // both convs: (XN + 25*WM*MT*128 words) * 4B = 102,656 B
    constexpr int SM1 = (8 * (5 * 8 * 40 + 8) + 25 * 2 * 2 * 128) * 4;
    constexpr int SM2 = (8 * (5 * 12 * 40 + 8) + 25 * 1 * 2 * 128) * 4;

    cudaFuncSetAttribute((const void*)k_conv_tc<64, 64, 4, 2, true>,
                         cudaFuncAttributeMaxDynamicSharedMemorySize, SM1);
    cudaFuncSetAttribute((const void*)k_conv_tc<32, 32, 8, 1, false>,
                         cudaFuncAttributeMaxDynamicSharedMemorySize, SM2);

    // One-time host-side resources (created on first, non-captured call).
    static cudaStream_t s1 = nullptr, s2 = nullptr;
    static cudaEvent_t e0 = nullptr, eX = nullptr, eA = nullptr,
                       e1a = nullptr, e2a = nullptr;
    if (s1 == nullptr) {
        cudaStreamCreateWithFlags(&s1, cudaStreamNonBlocking);
        cudaStreamCreateWithFlags(&s2, cudaStreamNonBlocking);
        cudaEventCreateWithFlags(&e0, cudaEventDisableTiming);
        cudaEventCreateWithFlags(&eX, cudaEventDisableTiming);
        cudaEventCreateWithFlags(&eA, cudaEventDisableTiming);
        cudaEventCreateWithFlags(&e1a, cudaEventDisableTiming);
        cudaEventCreateWithFlags(&e2a, cudaEventDisableTiming);
    }

    cudaEventRecord(e0, (cudaStream_t)0);

    // s2: build padded fp16 conv1 input + zero conv2-input pads
    cudaStreamWaitEvent(s2, e0, 0);
    k_xh<<<4096, 256, 0, s2>>>(x, xh1);
    k_zero<<<2048, 256, 0, s2>>>(xh2, BATCH * 32 * 36 * 38 * 40 / 4);
    cudaEventRecord(eX, s2);

    // s1: attention path (overlaps conv1)
    cudaStreamWaitEvent(s1, e0, 0);
    k_pre<<<S / 256, 256, 0, s1>>>(basis, mixer, wq, wk, wv);
    k_attn<<<(BATCH * S) / 256, 256, 0, s1>>>(x, wv, alpha, out);
    cudaEventRecord(eA, s1);

    // main: weight permutes
    k_wtp<128, 64, 2, 2><<<256, 256>>>(c1w, wtp1);
    k_wtp<64, 32, 1, 2><<<64, 256>>>(c2w, wtp2);

    // main: conv1a  h in [0,16)
    cudaStreamWaitEvent((cudaStream_t)0, eX, 0);
    k_conv_tc<64, 64, 4, 2, true>
        <<<dim3(8, 16, 4), 256, SM1>>>(xh1, wtp1, c1b, xh2, 0);
    cudaEventRecord(e1a, (cudaStream_t)0);

    // main: conv1b  h in [16,32)
    k_conv_tc<64, 64, 4, 2, true>
        <<<dim3(8, 16, 4), 256, SM1>>>(xh1, wtp1, c1b, xh2, 16);

    // s2: conv2a  h in [0,14) — needs conv1a rows (<=15), attn-out, zero2 (s2-ordered)
    cudaStreamWaitEvent(s2, e1a, 0);
    cudaStreamWaitEvent(s2, eA, 0);
    k_conv_tc<32, 32, 8, 1, false>
        <<<dim3(4, 14, 4), 256, SM2, s2>>>(xh2, wtp2, c2b, out, 0);
    cudaEventRecord(e2a, s2);

    // main: conv2b  h in [14,32) — after conv1b (stream order) + attn
    cudaStreamWaitEvent((cudaStream_t)0, eA, 0);
    k_conv_tc<32, 32, 8, 1, false>
        <<<dim3(4, 18, 4), 256, SM2>>>(xh2, wtp2, c2b, out, 14);

    // rejoin s2 into origin stream so the captured graph is complete
    cudaStreamWaitEvent((cudaStream_t)0, e2a, 0);
}